// round 7
// baseline (speedup 1.0000x reference)
#include <cuda_runtime.h>
#include <math.h>
#include <stdint.h>

#define NJ 34
#define NV 500000
#define NB 32
#define NQF (NV * 3 / 4)          // 375000 output float4s per batch plane
#define BLK 256
#define TILES 3
#define VPB (BLK * TILES)         // 768 vertices per block
#define NBLOCKS ((NV + VPB - 1) / VPB)   // 652
#define F4B (VPB * 3 / 4)         // 576 float4s per plane per block
#define W_STRIDE 1088             // floats of weights per warp-tile (32*34)

__constant__ int c_parents[NJ] = {
    -1, 0, 1, 2, 2, 4, 5, 6, 7, 8, 9, 7, 11, 12, 7, 14, 15, 2,
    17, 18, 19, 20, 21, 22, 20, 24, 25, 20, 27, 28, 0, 30, 0, 32
};

__global__ __launch_bounds__(BLK) void fused_lbs_kernel(
    const float* __restrict__ pose,
    const float* __restrict__ joints,
    const float* __restrict__ weights,
    const float* __restrict__ v_template,
    const float* __restrict__ local_adjust,
    const float* __restrict__ disp,
    const float* __restrict__ scale,
    const float* __restrict__ est,
    float4* __restrict__ out)
{
    __shared__ __align__(16) float sA[NJ * 12];
    __shared__ float sBase[NB * 4];
    __shared__ __align__(16) float sW[8 * W_STRIDE];   // 34 KB weight staging
    __shared__ __align__(16) float sVP[VPB * 3];       // 9 KB posed verts

    // phase-0 scratch aliased inside sW (dead until staging starts)
    float* sT = sW;           // NJ*12 = 408 floats
    float* sJ = sW + 512;     // NJ*3

    const int t = threadIdx.x;
    const int w = t >> 5;
    const int l = t & 31;

    // ---- phase 0a: base table + joints ----
    if (t < NB * 3) {
        int b = t / 3, cc = t - b * 3;
        sBase[b * 4 + cc] = disp[cc] + est[t];
    } else if (t >= 96 && t < 96 + NB) {
        sBase[(t - 96) * 4 + 3] = 0.0f;
    }
    if (t < NJ * 3) sJ[t] = joints[t];
    __syncthreads();

    // ---- phase 0b: local transforms ----
    if (t < NJ) {
        float rx = pose[t * 3 + 0], ry = pose[t * 3 + 1], rz = pose[t * 3 + 2];
        float ang = sqrtf(rx * rx + ry * ry + rz * rz + 1e-8f);
        float inv = 1.0f / ang;
        float x = rx * inv, y = ry * inv, z = rz * inv;
        float s = sinf(ang), c = cosf(ang), oc = 1.0f - c;
        int p = c_parents[t];
        float tx = sJ[t * 3 + 0], ty = sJ[t * 3 + 1], tz = sJ[t * 3 + 2];
        if (p >= 0) { tx -= sJ[p * 3 + 0]; ty -= sJ[p * 3 + 1]; tz -= sJ[p * 3 + 2]; }
        float* T = sT + t * 12;
        T[0] = c + oc * x * x;      T[1] = oc * x * y - s * z;  T[2]  = oc * x * z + s * y;  T[3]  = tx;
        T[4] = oc * x * y + s * z;  T[5] = c + oc * y * y;      T[6]  = oc * y * z - s * x;  T[7]  = ty;
        T[8] = oc * x * z - s * y;  T[9] = oc * y * z + s * x;  T[10] = c + oc * z * z;      T[11] = tz;
    }
    __syncthreads();

    // ---- phase 0c: ancestor-chain composition -> A (scale folded) ----
    if (t < NJ) {
        int chain[16];
        int d = 0;
        for (int n = t; n >= 0; n = c_parents[n]) chain[d++] = n;
        float G[12];
        const float* Tr = sT + chain[d - 1] * 12;
        #pragma unroll
        for (int k = 0; k < 12; k++) G[k] = Tr[k];
        for (int k = d - 2; k >= 0; k--) {
            const float* Tc = sT + chain[k] * 12;
            float C[12];
            #pragma unroll
            for (int r = 0; r < 3; r++) {
                float g0 = G[r * 4 + 0], g1 = G[r * 4 + 1], g2 = G[r * 4 + 2], g3 = G[r * 4 + 3];
                C[r * 4 + 0] = g0 * Tc[0] + g1 * Tc[4] + g2 * Tc[8];
                C[r * 4 + 1] = g0 * Tc[1] + g1 * Tc[5] + g2 * Tc[9];
                C[r * 4 + 2] = g0 * Tc[2] + g1 * Tc[6] + g2 * Tc[10];
                C[r * 4 + 3] = g0 * Tc[3] + g1 * Tc[7] + g2 * Tc[11] + g3;
            }
            #pragma unroll
            for (int k2 = 0; k2 < 12; k2++) G[k2] = C[k2];
        }
        float sc = scale[0];
        float jx = sJ[t * 3 + 0], jy = sJ[t * 3 + 1], jz = sJ[t * 3 + 2];
        #pragma unroll
        for (int r = 0; r < 3; r++) {
            float tr = G[r * 4 + 0] * jx + G[r * 4 + 1] * jy + G[r * 4 + 2] * jz;
            sA[t * 12 + r * 4 + 0] = sc * G[r * 4 + 0];
            sA[t * 12 + r * 4 + 1] = sc * G[r * 4 + 1];
            sA[t * 12 + r * 4 + 2] = sc * G[r * 4 + 2];
            sA[t * 12 + r * 4 + 3] = sc * (G[r * 4 + 3] - tr);
        }
    }
    __syncthreads();   // sT/sJ dead; sW free for weight staging

    // ---- tiled skin with register-double-buffered weight staging ----
    const int block_base = blockIdx.x * VPB;
    const size_t f4_total = (size_t)NV * 34 / 4;
    const float4* srcw = (const float4*)weights;
    float4* dstw = (float4*)(sW + w * W_STRIDE);
    float4 pf[9];

    // prologue: load tile 0 into regs, then to shared
    {
        int wb = block_base + w * 32;
        if (wb < NV) {
            size_t f4b = (size_t)wb * 34 / 4;
            #pragma unroll
            for (int i = 0; i < 9; i++) {
                int idx = i * 32 + l;
                if (idx < 272 && f4b + idx < f4_total) pf[i] = __ldcs(srcw + f4b + idx);
            }
            #pragma unroll
            for (int i = 0; i < 9; i++) {
                int idx = i * 32 + l;
                if (idx < 272 && f4b + idx < f4_total) dstw[idx] = pf[i];
            }
        }
    }
    __syncwarp();

    #pragma unroll
    for (int ti = 0; ti < TILES; ti++) {
        // issue prefetch of next tile (latency hidden by compute below)
        int wbn = block_base + (ti + 1) * BLK + w * 32;
        if (ti + 1 < TILES && wbn < NV) {
            size_t f4b = (size_t)wbn * 34 / 4;
            #pragma unroll
            for (int i = 0; i < 9; i++) {
                int idx = i * 32 + l;
                if (idx < 272 && f4b + idx < f4_total) pf[i] = __ldcs(srcw + f4b + idx);
            }
        }

        // compute current tile from shared
        int v = block_base + ti * BLK + t;
        float vp0 = 0.0f, vp1 = 0.0f, vp2 = 0.0f;
        if (v < NV) {
            float T[12];
            #pragma unroll
            for (int k = 0; k < 12; k++) T[k] = 0.0f;

            const float2* wp = (const float2*)(sW + w * W_STRIDE + l * 34);
            #pragma unroll
            for (int k = 0; k < 17; k++) {
                float2 w2 = wp[k];
                {
                    const float* Aj = sA + (2 * k) * 12;
                    float a[12];
                    *(float4*)(a + 0) = *(const float4*)(Aj + 0);
                    *(float4*)(a + 4) = *(const float4*)(Aj + 4);
                    *(float4*)(a + 8) = *(const float4*)(Aj + 8);
                    #pragma unroll
                    for (int q = 0; q < 12; q++) T[q] += w2.x * a[q];
                }
                {
                    const float* Aj = sA + (2 * k + 1) * 12;
                    float a[12];
                    *(float4*)(a + 0) = *(const float4*)(Aj + 0);
                    *(float4*)(a + 4) = *(const float4*)(Aj + 4);
                    *(float4*)(a + 8) = *(const float4*)(Aj + 8);
                    #pragma unroll
                    for (int q = 0; q < 12; q++) T[q] += w2.y * a[q];
                }
            }

            const float* vtp = v_template + (size_t)v * 3;
            const float* lap = local_adjust + (size_t)v * 3;
            float vx = __ldcs(vtp + 0) + __ldcs(lap + 0);
            float vy = __ldcs(vtp + 1) + __ldcs(lap + 1);
            float vz = __ldcs(vtp + 2) + __ldcs(lap + 2);

            vp0 = T[0] * vx + T[1] * vy + T[2]  * vz + T[3];
            vp1 = T[4] * vx + T[5] * vy + T[6]  * vz + T[7];
            vp2 = T[8] * vx + T[9] * vy + T[10] * vz + T[11];
        }
        int li = ti * BLK + t;
        sVP[li * 3 + 0] = vp0;
        sVP[li * 3 + 1] = vp1;
        sVP[li * 3 + 2] = vp2;

        __syncwarp();   // all lanes done reading sW for this tile
        if (ti + 1 < TILES && wbn < NV) {
            size_t f4b = (size_t)wbn * 34 / 4;
            #pragma unroll
            for (int i = 0; i < 9; i++) {
                int idx = i * 32 + l;
                if (idx < 272 && f4b + idx < f4_total) dstw[idx] = pf[i];
            }
        }
        __syncwarp();
    }

    // ---- store phase: 9KB contiguous per plane per block ----
    __syncthreads();
    const int block_f4 = blockIdx.x * F4B;          // multiple of 3
    int nval = NQF - block_f4;
    if (nval > F4B) nval = F4B;

    const int b0i = w * 4;
    float bx[4], by[4], bz[4];
    #pragma unroll
    for (int p = 0; p < 4; p++) {
        bx[p] = sBase[(b0i + p) * 4 + 0];
        by[p] = sBase[(b0i + p) * 4 + 1];
        bz[p] = sBase[(b0i + p) * 4 + 2];
    }
    const float4* sVP4 = (const float4*)sVP;
    const int lm = l % 3;

    #pragma unroll
    for (int j = 0; j < 18; j++) {                  // F4B/32 = 18
        int r = j * 32 + l;
        if (r < nval) {
            float4 pv = sVP4[r];
            int m = lm + ((j * 32) % 3);            // (j*32)%3 is compile-time
            if (m >= 3) m -= 3;
            #pragma unroll
            for (int p = 0; p < 4; p++) {
                float s0 = (m == 0) ? bx[p] : ((m == 1) ? by[p] : bz[p]);
                float s1 = (m == 0) ? by[p] : ((m == 1) ? bz[p] : bx[p]);
                float s2 = (m == 0) ? bz[p] : ((m == 1) ? bx[p] : by[p]);
                float4 o;
                o.x = pv.x + s0; o.y = pv.y + s1; o.z = pv.z + s2; o.w = pv.w + s0;
                __stcs(out + (size_t)(b0i + p) * NQF + block_f4 + r, o);
            }
        }
    }
}

// ---------------------------------------------------------------------------
extern "C" void kernel_launch(void* const* d_in, const int* in_sizes, int n_in,
                              void* d_out, int out_size)
{
    const float* pose         = (const float*)d_in[0]; // (34,3)
    const float* joints       = (const float*)d_in[1]; // (34,3)
    const float* weights      = (const float*)d_in[2]; // (V,34)
    const float* v_template   = (const float*)d_in[3]; // (V,3)
    const float* local_adjust = (const float*)d_in[4]; // (V,3)
    const float* displacement = (const float*)d_in[5]; // (1,3)
    const float* scale        = (const float*)d_in[6]; // (1,)
    const float* est          = (const float*)d_in[7]; // (B,3)
    float* out = (float*)d_out;
    (void)in_sizes; (void)n_in; (void)out_size;

    fused_lbs_kernel<<<NBLOCKS, BLK>>>(pose, joints, weights, v_template,
                                       local_adjust, displacement, scale, est,
                                       (float4*)out);
}

// round 8
// speedup vs baseline: 1.0294x; 1.0294x over previous
#include <cuda_runtime.h>
#include <math.h>
#include <stdint.h>

#define NJ 34
#define NV 500000
#define NB 32
#define NQF (NV * 3 / 4)       // 375000 float4s per batch plane
#define BLK 256
#define NBLOCKS_A ((NV + BLK - 1) / BLK)   // 1954
#define F4_PER_BLK (BLK * 3 / 4)           // 192 f4 of v_posed per block
#define W_STRIDE 1088                       // floats of weights per warp (32*34)

__constant__ int c_parents[NJ] = {
    -1, 0, 1, 2, 2, 4, 5, 6, 7, 8, 9, 7, 11, 12, 7, 14, 15, 2,
    17, 18, 19, 20, 21, 22, 20, 24, 25, 20, 27, 28, 0, 30, 0, 32
};

__device__ float g_vp[NV * 3];   // posed vertices (6 MB, L2-resident)

// ---------------------------------------------------------------------------
// Kernel A: per-block joint prep + skinning -> g_vp   (read-bound)
// ---------------------------------------------------------------------------
__global__ __launch_bounds__(BLK) void skin_kernel(
    const float* __restrict__ pose,
    const float* __restrict__ joints,
    const float* __restrict__ weights,
    const float* __restrict__ v_template,
    const float* __restrict__ local_adjust,
    const float* __restrict__ scale)
{
    __shared__ __align__(16) float sA[NJ * 12];
    __shared__ __align__(16) float sW[8 * W_STRIDE];   // 34 KB staging
    __shared__ __align__(16) float sVP[BLK * 3];       // 3 KB posed verts

    float* sT = sW;           // phase-0 alias
    float* sJ = sW + 512;

    const int t = threadIdx.x;
    const int w = t >> 5;
    const int l = t & 31;

    if (t < NJ * 3) sJ[t] = joints[t];
    __syncthreads();

    if (t < NJ) {
        float rx = pose[t * 3 + 0], ry = pose[t * 3 + 1], rz = pose[t * 3 + 2];
        float ang = sqrtf(rx * rx + ry * ry + rz * rz + 1e-8f);
        float inv = 1.0f / ang;
        float x = rx * inv, y = ry * inv, z = rz * inv;
        float s = sinf(ang), c = cosf(ang), oc = 1.0f - c;
        int p = c_parents[t];
        float tx = sJ[t * 3 + 0], ty = sJ[t * 3 + 1], tz = sJ[t * 3 + 2];
        if (p >= 0) { tx -= sJ[p * 3 + 0]; ty -= sJ[p * 3 + 1]; tz -= sJ[p * 3 + 2]; }
        float* T = sT + t * 12;
        T[0] = c + oc * x * x;      T[1] = oc * x * y - s * z;  T[2]  = oc * x * z + s * y;  T[3]  = tx;
        T[4] = oc * x * y + s * z;  T[5] = c + oc * y * y;      T[6]  = oc * y * z - s * x;  T[7]  = ty;
        T[8] = oc * x * z - s * y;  T[9] = oc * y * z + s * x;  T[10] = c + oc * z * z;      T[11] = tz;
    }
    __syncthreads();

    if (t < NJ) {
        int chain[16];
        int d = 0;
        for (int n = t; n >= 0; n = c_parents[n]) chain[d++] = n;
        float G[12];
        const float* Tr = sT + chain[d - 1] * 12;
        #pragma unroll
        for (int k = 0; k < 12; k++) G[k] = Tr[k];
        for (int k = d - 2; k >= 0; k--) {
            const float* Tc = sT + chain[k] * 12;
            float C[12];
            #pragma unroll
            for (int r = 0; r < 3; r++) {
                float g0 = G[r * 4 + 0], g1 = G[r * 4 + 1], g2 = G[r * 4 + 2], g3 = G[r * 4 + 3];
                C[r * 4 + 0] = g0 * Tc[0] + g1 * Tc[4] + g2 * Tc[8];
                C[r * 4 + 1] = g0 * Tc[1] + g1 * Tc[5] + g2 * Tc[9];
                C[r * 4 + 2] = g0 * Tc[2] + g1 * Tc[6] + g2 * Tc[10];
                C[r * 4 + 3] = g0 * Tc[3] + g1 * Tc[7] + g2 * Tc[11] + g3;
            }
            #pragma unroll
            for (int k2 = 0; k2 < 12; k2++) G[k2] = C[k2];
        }
        float sc = scale[0];
        float jx = sJ[t * 3 + 0], jy = sJ[t * 3 + 1], jz = sJ[t * 3 + 2];
        #pragma unroll
        for (int r = 0; r < 3; r++) {
            float tr = G[r * 4 + 0] * jx + G[r * 4 + 1] * jy + G[r * 4 + 2] * jz;
            sA[t * 12 + r * 4 + 0] = sc * G[r * 4 + 0];
            sA[t * 12 + r * 4 + 1] = sc * G[r * 4 + 1];
            sA[t * 12 + r * 4 + 2] = sc * G[r * 4 + 2];
            sA[t * 12 + r * 4 + 3] = sc * (G[r * 4 + 3] - tr);
        }
    }
    __syncthreads();

    // warp-cooperative coalesced weight staging
    const int block_base = blockIdx.x * BLK;
    const int warp_base = block_base + w * 32;
    const int v = block_base + t;

    if (warp_base < NV) {
        const size_t f4_base = (size_t)warp_base * 34 / 4;
        const size_t f4_total = (size_t)NV * 34 / 4;
        const float4* srcw = (const float4*)weights;
        float4* dstw = (float4*)(sW + w * W_STRIDE);
        #pragma unroll
        for (int i = 0; i < 9; i++) {
            int idx = i * 32 + l;
            if (idx < 272 && f4_base + idx < f4_total)
                dstw[idx] = __ldcs(srcw + f4_base + idx);
        }
    }
    __syncwarp();

    float vp0 = 0.0f, vp1 = 0.0f, vp2 = 0.0f;
    if (v < NV) {
        float T[12];
        #pragma unroll
        for (int k = 0; k < 12; k++) T[k] = 0.0f;

        const float2* wp = (const float2*)(sW + w * W_STRIDE + l * 34);
        #pragma unroll
        for (int k = 0; k < 17; k++) {
            float2 w2 = wp[k];
            {
                const float* Aj = sA + (2 * k) * 12;
                float a[12];
                *(float4*)(a + 0) = *(const float4*)(Aj + 0);
                *(float4*)(a + 4) = *(const float4*)(Aj + 4);
                *(float4*)(a + 8) = *(const float4*)(Aj + 8);
                #pragma unroll
                for (int q = 0; q < 12; q++) T[q] += w2.x * a[q];
            }
            {
                const float* Aj = sA + (2 * k + 1) * 12;
                float a[12];
                *(float4*)(a + 0) = *(const float4*)(Aj + 0);
                *(float4*)(a + 4) = *(const float4*)(Aj + 4);
                *(float4*)(a + 8) = *(const float4*)(Aj + 8);
                #pragma unroll
                for (int q = 0; q < 12; q++) T[q] += w2.y * a[q];
            }
        }

        const float* vtp = v_template + (size_t)v * 3;
        const float* lap = local_adjust + (size_t)v * 3;
        float vx = __ldcs(vtp + 0) + __ldcs(lap + 0);
        float vy = __ldcs(vtp + 1) + __ldcs(lap + 1);
        float vz = __ldcs(vtp + 2) + __ldcs(lap + 2);

        vp0 = T[0] * vx + T[1] * vy + T[2]  * vz + T[3];
        vp1 = T[4] * vx + T[5] * vy + T[6]  * vz + T[7];
        vp2 = T[8] * vx + T[9] * vy + T[10] * vz + T[11];
    }

    __syncthreads();
    sVP[t * 3 + 0] = vp0;
    sVP[t * 3 + 1] = vp1;
    sVP[t * 3 + 2] = vp2;
    __syncthreads();

    // coalesced write of this block's 192 float4s of v_posed (keep in L2)
    if (t < F4_PER_BLK) {
        int block_f4 = blockIdx.x * F4_PER_BLK;
        if (block_f4 + t < NQF)
            ((float4*)g_vp)[block_f4 + t] = ((const float4*)sVP)[t];
    }
}

// ---------------------------------------------------------------------------
// Kernel B: broadcast. One thread per plane-float4; reads g_vp from L2,
// writes 32 planes. Rotated-addend table removes per-plane select logic.
// ---------------------------------------------------------------------------
__global__ __launch_bounds__(BLK) void bcast_kernel(
    const float* __restrict__ disp,
    const float* __restrict__ est,
    float4* __restrict__ out)
{
    __shared__ __align__(16) float4 sRot[3 * NB];   // [m][plane] addend

    int t = threadIdx.x;
    if (t < 3 * NB) {
        int m = t >> 5;          // t / 32
        int p = t & 31;          // t % 32
        float b0 = disp[0] + est[p * 3 + 0];
        float b1 = disp[1] + est[p * 3 + 1];
        float b2 = disp[2] + est[p * 3 + 2];
        float r0 = (m == 0) ? b0 : ((m == 1) ? b1 : b2);
        float r1 = (m == 0) ? b1 : ((m == 1) ? b2 : b0);
        float r2 = (m == 0) ? b2 : ((m == 1) ? b0 : b1);
        sRot[m * NB + p] = make_float4(r0, r1, r2, r0);
    }
    __syncthreads();

    int r = blockIdx.x * BLK + t;
    if (r >= NQF) return;

    float4 v = __ldg((const float4*)g_vp + r);
    int m = r % 3;
    const float4* rot = sRot + m * NB;

    #pragma unroll
    for (int b = 0; b < NB; b++) {
        float4 a = rot[b];
        float4 o;
        o.x = v.x + a.x; o.y = v.y + a.y; o.z = v.z + a.z; o.w = v.w + a.w;
        __stcs(out + (size_t)b * NQF + r, o);
    }
}

// ---------------------------------------------------------------------------
extern "C" void kernel_launch(void* const* d_in, const int* in_sizes, int n_in,
                              void* d_out, int out_size)
{
    const float* pose         = (const float*)d_in[0]; // (34,3)
    const float* joints       = (const float*)d_in[1]; // (34,3)
    const float* weights      = (const float*)d_in[2]; // (V,34)
    const float* v_template   = (const float*)d_in[3]; // (V,3)
    const float* local_adjust = (const float*)d_in[4]; // (V,3)
    const float* displacement = (const float*)d_in[5]; // (1,3)
    const float* scale        = (const float*)d_in[6]; // (1,)
    const float* est          = (const float*)d_in[7]; // (B,3)
    float* out = (float*)d_out;
    (void)in_sizes; (void)n_in; (void)out_size;

    skin_kernel<<<NBLOCKS_A, BLK>>>(pose, joints, weights, v_template,
                                    local_adjust, scale);

    int blocksB = (NQF + BLK - 1) / BLK;   // 1465
    bcast_kernel<<<blocksB, BLK>>>(displacement, est, (float4*)out);
}

// round 9
// speedup vs baseline: 1.0937x; 1.0625x over previous
#include <cuda_runtime.h>
#include <math.h>
#include <stdint.h>

#define NJ 34
#define NV 500000
#define NB 32
#define NQF (NV * 3 / 4)       // 375000 output float4s per batch plane
#define BLK 256
#define NBLOCKS ((NV + BLK - 1) / BLK)   // 1954
#define W_STRIDE 1088          // floats of weights per warp (32*34)

__constant__ int c_parents[NJ] = {
    -1, 0, 1, 2, 2, 4, 5, 6, 7, 8, 9, 7, 11, 12, 7, 14, 15, 2,
    17, 18, 19, 20, 21, 22, 20, 24, 25, 20, 27, 28, 0, 30, 0, 32
};

__global__ __launch_bounds__(BLK) void fused_lbs_kernel(
    const float* __restrict__ pose,
    const float* __restrict__ joints,
    const float* __restrict__ weights,
    const float* __restrict__ v_template,
    const float* __restrict__ local_adjust,
    const float* __restrict__ disp,
    const float* __restrict__ scale,
    const float* __restrict__ est,
    float4* __restrict__ out)
{
    __shared__ __align__(16) float sA[NJ * 12];
    __shared__ __align__(16) float4 sRot[3 * NB];      // rotated addend table
    __shared__ __align__(16) float sW[8 * W_STRIDE];   // 34 KB weight staging
    __shared__ __align__(16) float sVP[BLK * 3];       // warp-private slices

    // phase-0 scratch aliased inside sW (dead until staging)
    float* sT = sW;           // NJ*12 floats
    float* sJ = sW + 512;     // NJ*3 floats

    const int t = threadIdx.x;
    const int w = t >> 5;
    const int l = t & 31;

    // ---- phase 0a: rotated base table + joints ----
    if (t < 3 * NB) {
        int m = t >> 5;          // 0..2
        int p = t & 31;          // plane
        float b0 = disp[0] + est[p * 3 + 0];
        float b1 = disp[1] + est[p * 3 + 1];
        float b2 = disp[2] + est[p * 3 + 2];
        float r0 = (m == 0) ? b0 : ((m == 1) ? b1 : b2);
        float r1 = (m == 0) ? b1 : ((m == 1) ? b2 : b0);
        float r2 = (m == 0) ? b2 : ((m == 1) ? b0 : b1);
        sRot[m * NB + p] = make_float4(r0, r1, r2, r0);
    }
    if (t < NJ * 3) sJ[t] = joints[t];
    __syncthreads();

    // ---- phase 0b: local transforms ----
    if (t < NJ) {
        float rx = pose[t * 3 + 0], ry = pose[t * 3 + 1], rz = pose[t * 3 + 2];
        float ang = sqrtf(rx * rx + ry * ry + rz * rz + 1e-8f);
        float inv = 1.0f / ang;
        float x = rx * inv, y = ry * inv, z = rz * inv;
        float s = sinf(ang), c = cosf(ang), oc = 1.0f - c;
        int p = c_parents[t];
        float tx = sJ[t * 3 + 0], ty = sJ[t * 3 + 1], tz = sJ[t * 3 + 2];
        if (p >= 0) { tx -= sJ[p * 3 + 0]; ty -= sJ[p * 3 + 1]; tz -= sJ[p * 3 + 2]; }
        float* T = sT + t * 12;
        T[0] = c + oc * x * x;      T[1] = oc * x * y - s * z;  T[2]  = oc * x * z + s * y;  T[3]  = tx;
        T[4] = oc * x * y + s * z;  T[5] = c + oc * y * y;      T[6]  = oc * y * z - s * x;  T[7]  = ty;
        T[8] = oc * x * z - s * y;  T[9] = oc * y * z + s * x;  T[10] = c + oc * z * z;      T[11] = tz;
    }
    __syncthreads();

    // ---- phase 0c: ancestor-chain composition -> A (scale folded) ----
    if (t < NJ) {
        int chain[16];
        int d = 0;
        for (int n = t; n >= 0; n = c_parents[n]) chain[d++] = n;
        float G[12];
        const float* Tr = sT + chain[d - 1] * 12;
        #pragma unroll
        for (int k = 0; k < 12; k++) G[k] = Tr[k];
        for (int k = d - 2; k >= 0; k--) {
            const float* Tc = sT + chain[k] * 12;
            float C[12];
            #pragma unroll
            for (int r = 0; r < 3; r++) {
                float g0 = G[r * 4 + 0], g1 = G[r * 4 + 1], g2 = G[r * 4 + 2], g3 = G[r * 4 + 3];
                C[r * 4 + 0] = g0 * Tc[0] + g1 * Tc[4] + g2 * Tc[8];
                C[r * 4 + 1] = g0 * Tc[1] + g1 * Tc[5] + g2 * Tc[9];
                C[r * 4 + 2] = g0 * Tc[2] + g1 * Tc[6] + g2 * Tc[10];
                C[r * 4 + 3] = g0 * Tc[3] + g1 * Tc[7] + g2 * Tc[11] + g3;
            }
            #pragma unroll
            for (int k2 = 0; k2 < 12; k2++) G[k2] = C[k2];
        }
        float sc = scale[0];
        float jx = sJ[t * 3 + 0], jy = sJ[t * 3 + 1], jz = sJ[t * 3 + 2];
        #pragma unroll
        for (int r = 0; r < 3; r++) {
            float tr = G[r * 4 + 0] * jx + G[r * 4 + 1] * jy + G[r * 4 + 2] * jz;
            sA[t * 12 + r * 4 + 0] = sc * G[r * 4 + 0];
            sA[t * 12 + r * 4 + 1] = sc * G[r * 4 + 1];
            sA[t * 12 + r * 4 + 2] = sc * G[r * 4 + 2];
            sA[t * 12 + r * 4 + 3] = sc * (G[r * 4 + 3] - tr);
        }
    }
    __syncthreads();   // ONLY block-wide barrier after this point: none.

    // ======== warp-autonomous from here ========
    const int block_base = blockIdx.x * BLK;
    const int warp_base = block_base + w * 32;
    if (warp_base >= NV) return;                  // NV % 32 == 0

    // ---- weight staging: coalesced LDG.128 -> shared (warp-local) ----
    {
        const size_t f4_base = (size_t)warp_base * 34 / 4;
        const float4* srcw = (const float4*)weights;
        float4* dstw = (float4*)(sW + w * W_STRIDE);
        #pragma unroll
        for (int i = 0; i < 9; i++) {
            int idx = i * 32 + l;
            if (idx < 272) dstw[idx] = __ldcs(srcw + f4_base + idx);
        }
    }
    __syncwarp();

    // ---- skin (identical math to R5) ----
    const int v = warp_base + l;
    float T[12];
    #pragma unroll
    for (int k = 0; k < 12; k++) T[k] = 0.0f;

    const float2* wp = (const float2*)(sW + w * W_STRIDE + l * 34);
    #pragma unroll
    for (int k = 0; k < 17; k++) {
        float2 w2 = wp[k];
        {
            const float* Aj = sA + (2 * k) * 12;
            float a[12];
            *(float4*)(a + 0) = *(const float4*)(Aj + 0);
            *(float4*)(a + 4) = *(const float4*)(Aj + 4);
            *(float4*)(a + 8) = *(const float4*)(Aj + 8);
            #pragma unroll
            for (int q = 0; q < 12; q++) T[q] += w2.x * a[q];
        }
        {
            const float* Aj = sA + (2 * k + 1) * 12;
            float a[12];
            *(float4*)(a + 0) = *(const float4*)(Aj + 0);
            *(float4*)(a + 4) = *(const float4*)(Aj + 4);
            *(float4*)(a + 8) = *(const float4*)(Aj + 8);
            #pragma unroll
            for (int q = 0; q < 12; q++) T[q] += w2.y * a[q];
        }
    }

    const float* vtp = v_template + (size_t)v * 3;
    const float* lap = local_adjust + (size_t)v * 3;
    float vx = __ldcs(vtp + 0) + __ldcs(lap + 0);
    float vy = __ldcs(vtp + 1) + __ldcs(lap + 1);
    float vz = __ldcs(vtp + 2) + __ldcs(lap + 2);

    float vp0 = T[0] * vx + T[1] * vy + T[2]  * vz + T[3];
    float vp1 = T[4] * vx + T[5] * vy + T[6]  * vz + T[7];
    float vp2 = T[8] * vx + T[9] * vy + T[10] * vz + T[11];

    // ---- warp-private staging (384B slice) ----
    float* sVPw = sVP + w * 96;
    sVPw[l * 3 + 0] = vp0;
    sVPw[l * 3 + 1] = vp1;
    sVPw[l * 3 + 2] = vp2;
    __syncwarp();

    // ---- warp-autonomous batched stores: lanes 0..23, 24 f4 x 32 planes ----
    if (l < 24) {
        const int warp_f4 = warp_base * 3 / 4;     // divisible by 24
        const int m = l % 3;
        const float4 pv = ((const float4*)sVPw)[l];
        const float4* rot = sRot + m * NB;
        float4* obase = out + warp_f4 + l;
        #pragma unroll
        for (int b = 0; b < NB; b++) {
            float4 a = rot[b];
            float4 o;
            o.x = pv.x + a.x; o.y = pv.y + a.y; o.z = pv.z + a.z; o.w = pv.w + a.w;
            __stcs(obase + (size_t)b * NQF, o);
        }
    }
}

// ---------------------------------------------------------------------------
extern "C" void kernel_launch(void* const* d_in, const int* in_sizes, int n_in,
                              void* d_out, int out_size)
{
    const float* pose         = (const float*)d_in[0]; // (34,3)
    const float* joints       = (const float*)d_in[1]; // (34,3)
    const float* weights      = (const float*)d_in[2]; // (V,34)
    const float* v_template   = (const float*)d_in[3]; // (V,3)
    const float* local_adjust = (const float*)d_in[4]; // (V,3)
    const float* displacement = (const float*)d_in[5]; // (1,3)
    const float* scale        = (const float*)d_in[6]; // (1,)
    const float* est          = (const float*)d_in[7]; // (B,3)
    float* out = (float*)d_out;
    (void)in_sizes; (void)n_in; (void)out_size;

    fused_lbs_kernel<<<NBLOCKS, BLK>>>(pose, joints, weights, v_template,
                                       local_adjust, displacement, scale, est,
                                       (float4*)out);
}

// round 10
// speedup vs baseline: 1.1820x; 1.0807x over previous
#include <cuda_runtime.h>
#include <math.h>
#include <stdint.h>

#define NJ 34
#define NV 500000
#define NB 32
#define NQF (NV * 3 / 4)       // 375000 output float4s per batch plane
#define BLK 128
#define NWARPS (BLK / 32)      // 4
#define NBLOCKS ((NV + BLK - 1) / BLK)   // 3907
#define F4_PER_BLK (BLK * 3 / 4)         // 96 float4s per plane per block
#define W_STRIDE 1088          // floats of weights per warp (32*34)

__constant__ int c_parents[NJ] = {
    -1, 0, 1, 2, 2, 4, 5, 6, 7, 8, 9, 7, 11, 12, 7, 14, 15, 2,
    17, 18, 19, 20, 21, 22, 20, 24, 25, 20, 27, 28, 0, 30, 0, 32
};

__global__ __launch_bounds__(BLK) void fused_lbs_kernel(
    const float* __restrict__ pose,
    const float* __restrict__ joints,
    const float* __restrict__ weights,
    const float* __restrict__ v_template,
    const float* __restrict__ local_adjust,
    const float* __restrict__ disp,
    const float* __restrict__ scale,
    const float* __restrict__ est,
    float4* __restrict__ out)
{
    __shared__ __align__(16) float sA[NJ * 12];
    __shared__ float sBase[NB * 4];
    __shared__ __align__(16) float sW[NWARPS * W_STRIDE];  // 17 KB staging
    __shared__ __align__(16) float sVP[BLK * 3];           // 1.5 KB posed verts

    // phase-0 scratch aliased inside sW (dead until staging)
    float* sT = sW;           // NJ*12 = 408 floats
    float* sJ = sW + 512;     // NJ*3

    const int t = threadIdx.x;
    const int w = t >> 5;
    const int l = t & 31;

    // ---- phase 0a: base table + joints ----
    if (t < NB * 3) {
        int b = t / 3, cc = t - b * 3;
        sBase[b * 4 + cc] = disp[cc] + est[t];
    } else if (t >= 96 && t < 96 + NB) {
        sBase[(t - 96) * 4 + 3] = 0.0f;
    }
    if (t < NJ * 3) sJ[t] = joints[t];
    __syncthreads();

    // ---- phase 0b: local transforms ----
    if (t < NJ) {
        float rx = pose[t * 3 + 0], ry = pose[t * 3 + 1], rz = pose[t * 3 + 2];
        float ang = sqrtf(rx * rx + ry * ry + rz * rz + 1e-8f);
        float inv = 1.0f / ang;
        float x = rx * inv, y = ry * inv, z = rz * inv;
        float s = sinf(ang), c = cosf(ang), oc = 1.0f - c;
        int p = c_parents[t];
        float tx = sJ[t * 3 + 0], ty = sJ[t * 3 + 1], tz = sJ[t * 3 + 2];
        if (p >= 0) { tx -= sJ[p * 3 + 0]; ty -= sJ[p * 3 + 1]; tz -= sJ[p * 3 + 2]; }
        float* T = sT + t * 12;
        T[0] = c + oc * x * x;      T[1] = oc * x * y - s * z;  T[2]  = oc * x * z + s * y;  T[3]  = tx;
        T[4] = oc * x * y + s * z;  T[5] = c + oc * y * y;      T[6]  = oc * y * z - s * x;  T[7]  = ty;
        T[8] = oc * x * z - s * y;  T[9] = oc * y * z + s * x;  T[10] = c + oc * z * z;      T[11] = tz;
    }
    __syncthreads();

    // ---- phase 0c: ancestor-chain composition -> A (scale folded) ----
    if (t < NJ) {
        int chain[16];
        int d = 0;
        for (int n = t; n >= 0; n = c_parents[n]) chain[d++] = n;
        float G[12];
        const float* Tr = sT + chain[d - 1] * 12;
        #pragma unroll
        for (int k = 0; k < 12; k++) G[k] = Tr[k];
        for (int k = d - 2; k >= 0; k--) {
            const float* Tc = sT + chain[k] * 12;
            float C[12];
            #pragma unroll
            for (int r = 0; r < 3; r++) {
                float g0 = G[r * 4 + 0], g1 = G[r * 4 + 1], g2 = G[r * 4 + 2], g3 = G[r * 4 + 3];
                C[r * 4 + 0] = g0 * Tc[0] + g1 * Tc[4] + g2 * Tc[8];
                C[r * 4 + 1] = g0 * Tc[1] + g1 * Tc[5] + g2 * Tc[9];
                C[r * 4 + 2] = g0 * Tc[2] + g1 * Tc[6] + g2 * Tc[10];
                C[r * 4 + 3] = g0 * Tc[3] + g1 * Tc[7] + g2 * Tc[11] + g3;
            }
            #pragma unroll
            for (int k2 = 0; k2 < 12; k2++) G[k2] = C[k2];
        }
        float sc = scale[0];
        float jx = sJ[t * 3 + 0], jy = sJ[t * 3 + 1], jz = sJ[t * 3 + 2];
        #pragma unroll
        for (int r = 0; r < 3; r++) {
            float tr = G[r * 4 + 0] * jx + G[r * 4 + 1] * jy + G[r * 4 + 2] * jz;
            sA[t * 12 + r * 4 + 0] = sc * G[r * 4 + 0];
            sA[t * 12 + r * 4 + 1] = sc * G[r * 4 + 1];
            sA[t * 12 + r * 4 + 2] = sc * G[r * 4 + 2];
            sA[t * 12 + r * 4 + 3] = sc * (G[r * 4 + 3] - tr);
        }
    }
    __syncthreads();   // sT/sJ dead; sW free for weight staging

    // ---- phase 1a: warp-cooperative coalesced weight staging ----
    const int block_base = blockIdx.x * BLK;
    const int warp_base = block_base + w * 32;
    const int v = block_base + t;

    if (warp_base < NV) {
        const size_t f4_base = (size_t)warp_base * 34 / 4;
        const size_t f4_total = (size_t)NV * 34 / 4;
        const float4* srcw = (const float4*)weights;
        float4* dstw = (float4*)(sW + w * W_STRIDE);
        #pragma unroll
        for (int i = 0; i < 9; i++) {
            int idx = i * 32 + l;
            if (idx < 272 && f4_base + idx < f4_total)
                dstw[idx] = __ldcs(srcw + f4_base + idx);
        }
    }
    __syncwarp();

    // ---- phase 1b: skin (identical math to R5) ----
    float vp0 = 0.0f, vp1 = 0.0f, vp2 = 0.0f;
    if (v < NV) {
        float T[12];
        #pragma unroll
        for (int k = 0; k < 12; k++) T[k] = 0.0f;

        const float2* wp = (const float2*)(sW + w * W_STRIDE + l * 34);
        #pragma unroll
        for (int k = 0; k < 17; k++) {
            float2 w2 = wp[k];
            {
                const float* Aj = sA + (2 * k) * 12;
                float a[12];
                *(float4*)(a + 0) = *(const float4*)(Aj + 0);
                *(float4*)(a + 4) = *(const float4*)(Aj + 4);
                *(float4*)(a + 8) = *(const float4*)(Aj + 8);
                #pragma unroll
                for (int q = 0; q < 12; q++) T[q] += w2.x * a[q];
            }
            {
                const float* Aj = sA + (2 * k + 1) * 12;
                float a[12];
                *(float4*)(a + 0) = *(const float4*)(Aj + 0);
                *(float4*)(a + 4) = *(const float4*)(Aj + 4);
                *(float4*)(a + 8) = *(const float4*)(Aj + 8);
                #pragma unroll
                for (int q = 0; q < 12; q++) T[q] += w2.y * a[q];
            }
        }

        const float* vtp = v_template + (size_t)v * 3;
        const float* lap = local_adjust + (size_t)v * 3;
        float vx = __ldcs(vtp + 0) + __ldcs(lap + 0);
        float vy = __ldcs(vtp + 1) + __ldcs(lap + 1);
        float vz = __ldcs(vtp + 2) + __ldcs(lap + 2);

        vp0 = T[0] * vx + T[1] * vy + T[2]  * vz + T[3];
        vp1 = T[4] * vx + T[5] * vy + T[6]  * vz + T[7];
        vp2 = T[8] * vx + T[9] * vy + T[10] * vz + T[11];
    }

    // ---- phase 2: stage + batched coalesced stores (R5 pattern) ----
    __syncthreads();
    sVP[t * 3 + 0] = vp0;
    sVP[t * 3 + 1] = vp1;
    sVP[t * 3 + 2] = vp2;
    __syncthreads();

    if (t < F4_PER_BLK) {
        int block_f4 = blockIdx.x * F4_PER_BLK;      // multiple of 3
        int valid = NQF - block_f4;
        if (t < valid) {
            float4 pv = ((const float4*)sVP)[t];
            int m = t % 3;
            #pragma unroll
            for (int b = 0; b < NB; b++) {
                float b0 = sBase[b * 4 + 0];
                float b1 = sBase[b * 4 + 1];
                float b2 = sBase[b * 4 + 2];
                float s0 = (m == 0) ? b0 : ((m == 1) ? b1 : b2);
                float s1 = (m == 0) ? b1 : ((m == 1) ? b2 : b0);
                float s2 = (m == 0) ? b2 : ((m == 1) ? b0 : b1);
                float4 o;
                o.x = pv.x + s0; o.y = pv.y + s1; o.z = pv.z + s2; o.w = pv.w + s0;
                __stcs(out + (size_t)b * NQF + block_f4 + t, o);
            }
        }
    }
}

// ---------------------------------------------------------------------------
extern "C" void kernel_launch(void* const* d_in, const int* in_sizes, int n_in,
                              void* d_out, int out_size)
{
    const float* pose         = (const float*)d_in[0]; // (34,3)
    const float* joints       = (const float*)d_in[1]; // (34,3)
    const float* weights      = (const float*)d_in[2]; // (V,34)
    const float* v_template   = (const float*)d_in[3]; // (V,3)
    const float* local_adjust = (const float*)d_in[4]; // (V,3)
    const float* displacement = (const float*)d_in[5]; // (1,3)
    const float* scale        = (const float*)d_in[6]; // (1,)
    const float* est          = (const float*)d_in[7]; // (B,3)
    float* out = (float*)d_out;
    (void)in_sizes; (void)n_in; (void)out_size;

    fused_lbs_kernel<<<NBLOCKS, BLK>>>(pose, joints, weights, v_template,
                                       local_adjust, displacement, scale, est,
                                       (float4*)out);
}